// round 1
// baseline (speedup 1.0000x reference)
#include <cuda_runtime.h>
#include <cuda_bf16.h>
#include <cstdint>

// Problem constants
#define BATCH 4
#define SEQ   2048
#define DM    1024        // d_model
#define NH    16          // heads
#define HD    64          // head dim
#define M_ROWS (BATCH*SEQ)   // 8192

// Scratch (device globals; no allocation allowed)
__device__ float g_qkv[(size_t)M_ROWS * 3 * DM];   // [B*T, 3*C]  (3,H,hd packed in last dim)
__device__ float g_y[(size_t)M_ROWS * DM];         // [B*T, C]

// ---------------------------------------------------------------------------
// SGEMM with bias: C[M,N] = A[M,K] @ B[K,N] + bias[N]
// 128x128 tile, BK=8, 256 threads, 8x8 micro-tile. Requires M%128==0, N%128==0, K%8==0.
// ---------------------------------------------------------------------------
__global__ __launch_bounds__(256) void sgemm_bias_kernel(
    const float* __restrict__ A, const float* __restrict__ B,
    const float* __restrict__ bias, float* __restrict__ C,
    int M, int N, int K)
{
    __shared__ float As[8][128];
    __shared__ float Bs[8][128];

    const int tid = threadIdx.x;
    const int bm = blockIdx.y * 128;
    const int bn = blockIdx.x * 128;

    const int arow = tid >> 1;          // 0..127
    const int acol = (tid & 1) * 4;     // 0 or 4
    const int brow = tid >> 5;          // 0..7
    const int bcol = (tid & 31) * 4;    // 0..124

    const int tr = (tid >> 4) * 8;      // 0..120
    const int tc = (tid & 15) * 8;      // 0..120

    const float* Aptr = A + (size_t)(bm + arow) * K + acol;
    const float* Bptr = B + (size_t)brow * N + bn + bcol;

    float acc[8][8];
#pragma unroll
    for (int i = 0; i < 8; i++)
#pragma unroll
        for (int j = 0; j < 8; j++) acc[i][j] = 0.f;

    for (int k0 = 0; k0 < K; k0 += 8) {
        float4 a4 = *(const float4*)(Aptr + k0);
        As[acol + 0][arow] = a4.x;
        As[acol + 1][arow] = a4.y;
        As[acol + 2][arow] = a4.z;
        As[acol + 3][arow] = a4.w;
        *(float4*)&Bs[brow][bcol] = *(const float4*)(Bptr + (size_t)k0 * N);
        __syncthreads();

#pragma unroll
        for (int kk = 0; kk < 8; kk++) {
            float ar[8], br[8];
            *(float4*)&ar[0] = *(const float4*)&As[kk][tr];
            *(float4*)&ar[4] = *(const float4*)&As[kk][tr + 4];
            *(float4*)&br[0] = *(const float4*)&Bs[kk][tc];
            *(float4*)&br[4] = *(const float4*)&Bs[kk][tc + 4];
#pragma unroll
            for (int i = 0; i < 8; i++)
#pragma unroll
                for (int j = 0; j < 8; j++)
                    acc[i][j] += ar[i] * br[j];
        }
        __syncthreads();
    }

#pragma unroll
    for (int i = 0; i < 8; i++) {
        float* crow = C + (size_t)(bm + tr + i) * N + bn + tc;
#pragma unroll
        for (int j = 0; j < 8; j += 4) {
            float4 o;
            o.x = acc[i][j + 0] + bias[bn + tc + j + 0];
            o.y = acc[i][j + 1] + bias[bn + tc + j + 1];
            o.z = acc[i][j + 2] + bias[bn + tc + j + 2];
            o.w = acc[i][j + 3] + bias[bn + tc + j + 3];
            *(float4*)(crow + j) = o;
        }
    }
}

// ---------------------------------------------------------------------------
// Flash attention (causal, fp32 online softmax).
// grid = (T/64, H, B); block = 64 threads; thread t owns query row t of the tile.
// qkv layout: [B*T, 3*C] with inner dim ordered (sel, head, hd).
// Output y: [B*T, C] with inner dim (head, hd).
// smem: K tile 16KB + V tile 16KB + score tile 16KB = 48KB exactly.
// ---------------------------------------------------------------------------
__global__ __launch_bounds__(64) void flash_attn_kernel(
    const float* __restrict__ qkv, float* __restrict__ y)
{
    __shared__ float ks[64][64];
    __shared__ float vs[64][64];
    __shared__ float ss[64][64];   // transposed: ss[key][query_row] -> conflict-free

    const int row = threadIdx.x;            // query row within tile (0..63)
    const int qt0 = blockIdx.x * 64;
    const int h   = blockIdx.y;
    const int b   = blockIdx.z;
    const int qi  = qt0 + row;              // global query index
    const float scale = 0.125f;             // 1/sqrt(64)

    // Load this thread's query row into registers (64 floats)
    float4 q[16];
    {
        const float* qptr = qkv + ((size_t)(b * SEQ + qi) * 3 * DM) + h * HD;
#pragma unroll
        for (int i = 0; i < 16; i++) q[i] = ((const float4*)qptr)[i];
    }

    float o[64];
#pragma unroll
    for (int d = 0; d < 64; d++) o[d] = 0.f;
    float m = -1e30f, l = 0.f;

    const int ntiles = qt0 / 64 + 1;        // causal: key tiles 0..qt0/64
    for (int kt = 0; kt < ntiles; kt++) {
        const int kt0 = kt * 64;
        // Cooperative tile load: thread `row` loads key/value row (kt0+row)
        {
            const float* kptr = qkv + ((size_t)(b * SEQ + kt0 + row) * 3 * DM) + DM + h * HD;
            const float* vptr = kptr + DM;
#pragma unroll
            for (int i = 0; i < 16; i++) {
                ((float4*)ks[row])[i] = ((const float4*)kptr)[i];
                ((float4*)vs[row])[i] = ((const float4*)vptr)[i];
            }
        }
        __syncthreads();

        // Pass 1: scores for all 64 keys (broadcast reads of ks rows)
        float mt = -1e30f;
        for (int j = 0; j < 64; j++) {
            const float4* kk = (const float4*)ks[j];
            float s0 = 0.f, s1 = 0.f, s2 = 0.f, s3 = 0.f;
#pragma unroll
            for (int i = 0; i < 16; i++) {
                float4 k4 = kk[i];
                float4 qv = q[i];
                s0 += qv.x * k4.x;
                s1 += qv.y * k4.y;
                s2 += qv.z * k4.z;
                s3 += qv.w * k4.w;
            }
            float s = ((s0 + s1) + (s2 + s3)) * scale;
            if (kt0 + j > qi) s = -1e30f;   // causal mask
            ss[j][row] = s;
            mt = fmaxf(mt, s);
        }

        // Online softmax rescale
        const float mnew = fmaxf(m, mt);
        const float corr = __expf(m - mnew);
        l *= corr;
#pragma unroll
        for (int d = 0; d < 64; d++) o[d] *= corr;
        m = mnew;

        // Pass 2: exp + PV accumulation
        for (int j = 0; j < 64; j++) {
            const float p = __expf(ss[j][row] - mnew);
            l += p;
            const float4* vv = (const float4*)vs[j];
#pragma unroll
            for (int i = 0; i < 16; i++) {
                float4 v4 = vv[i];
                o[4 * i + 0] += p * v4.x;
                o[4 * i + 1] += p * v4.y;
                o[4 * i + 2] += p * v4.z;
                o[4 * i + 3] += p * v4.w;
            }
        }
        __syncthreads();
    }

    const float inv = 1.f / l;
    float* yptr = y + (size_t)(b * SEQ + qi) * DM + h * HD;
#pragma unroll
    for (int d = 0; d < 64; d += 4) {
        float4 t;
        t.x = o[d + 0] * inv;
        t.y = o[d + 1] * inv;
        t.z = o[d + 2] * inv;
        t.w = o[d + 3] * inv;
        *(float4*)(yptr + d) = t;
    }
}

// ---------------------------------------------------------------------------
// Launch
// ---------------------------------------------------------------------------
extern "C" void kernel_launch(void* const* d_in, const int* in_sizes, int n_in,
                              void* d_out, int out_size)
{
    (void)in_sizes; (void)n_in; (void)out_size;
    const float* x      = (const float*)d_in[0];
    const float* w_qkv  = (const float*)d_in[1];
    const float* b_qkv  = (const float*)d_in[2];
    const float* w_proj = (const float*)d_in[3];
    const float* b_proj = (const float*)d_in[4];
    float* out = (float*)d_out;

    float* qkv = nullptr;
    float* y   = nullptr;
    cudaGetSymbolAddress((void**)&qkv, g_qkv);
    cudaGetSymbolAddress((void**)&y,   g_y);

    // 1) QKV projection: [8192,1024] @ [1024,3072] + b
    sgemm_bias_kernel<<<dim3(3 * DM / 128, M_ROWS / 128), 256>>>(
        x, w_qkv, b_qkv, qkv, M_ROWS, 3 * DM, DM);

    // 2) Causal flash attention
    flash_attn_kernel<<<dim3(SEQ / 64, NH, BATCH), 64>>>(qkv, y);

    // 3) Output projection: [8192,1024] @ [1024,1024] + b
    sgemm_bias_kernel<<<dim3(DM / 128, M_ROWS / 128), 256>>>(
        y, w_proj, b_proj, out, M_ROWS, DM, DM);
}

// round 2
// speedup vs baseline: 1.3885x; 1.3885x over previous
#include <cuda_runtime.h>
#include <cuda_bf16.h>
#include <cstdint>

// Problem constants
#define BATCH 4
#define SEQ   2048
#define DM    1024
#define NH    16
#define HD    64
#define M_ROWS (BATCH*SEQ)   // 8192

// Scratch (device globals; no allocation allowed)
__device__ float g_qkv[(size_t)M_ROWS * 3 * DM];   // [B*T, 3*C] (sel, head, hd)
__device__ float g_y[(size_t)M_ROWS * DM];         // [B*T, C]

__device__ __forceinline__ uint32_t f2tf(float f) {
    uint32_t u;
    asm("cvt.rna.tf32.f32 %0, %1;" : "=r"(u) : "f"(f));
    return u;
}

// ---------------------------------------------------------------------------
// TF32 tensor-core GEMM with bias: C[M,N] = A[M,K] @ B[K,N] + bias[N]
// 128x128 block tile, BK=16 double-buffered, 256 thr (8 warps 4x2),
// warp tile 32x64 (2x8 grid of m16n8k8 mma). Requires M%128==N%128==0, K%16==0.
// ---------------------------------------------------------------------------
#define TFS 136   // smem row stride (padding: conflict-free fragment loads)

__global__ __launch_bounds__(256) void tf32_gemm_bias(
    const float* __restrict__ A, const float* __restrict__ B,
    const float* __restrict__ bias, float* __restrict__ C,
    int M, int N, int K)
{
    __shared__ uint32_t As[2][16][TFS];
    __shared__ uint32_t Bs[2][16][TFS];

    const int tid  = threadIdx.x;
    const int lane = tid & 31;
    const int wid  = tid >> 5;
    const int gid  = lane >> 2;   // group id (row within mma)
    const int tig  = lane & 3;    // thread in group (col within mma)
    const int wm   = (wid & 3) * 32;   // warp M offset
    const int wn   = (wid >> 2) * 64;  // warp N offset
    const int bm   = blockIdx.y * 128;
    const int bn   = blockIdx.x * 128;

    // Global-load indexing
    const int ar = tid >> 2;        // A row 0..63 (and +64)
    const int ac = (tid & 3) * 4;   // A col 0,4,8,12
    const int br = tid >> 4;        // B row 0..15
    const int bc = (tid & 15) * 4;  // B col 0..60 (and +64)

    const float* Ap = A + (size_t)(bm + ar) * K + ac;
    const float* Bp = B + (size_t)br * N + bn + bc;

    float acc[2][8][4];
#pragma unroll
    for (int mt = 0; mt < 2; mt++)
#pragma unroll
        for (int nt = 0; nt < 8; nt++)
#pragma unroll
            for (int i = 0; i < 4; i++) acc[mt][nt][i] = 0.f;

    const int ntiles = K / 16;
    float4 pa0, pa1, pb0, pb1;

    // Preload tile 0 into buffer 0
    {
        pa0 = *(const float4*)(Ap);
        pa1 = *(const float4*)(Ap + (size_t)64 * K);
        pb0 = *(const float4*)(Bp);
        pb1 = *(const float4*)(Bp + 64);
        As[0][ac + 0][ar]      = f2tf(pa0.x);
        As[0][ac + 1][ar]      = f2tf(pa0.y);
        As[0][ac + 2][ar]      = f2tf(pa0.z);
        As[0][ac + 3][ar]      = f2tf(pa0.w);
        As[0][ac + 0][ar + 64] = f2tf(pa1.x);
        As[0][ac + 1][ar + 64] = f2tf(pa1.y);
        As[0][ac + 2][ar + 64] = f2tf(pa1.z);
        As[0][ac + 3][ar + 64] = f2tf(pa1.w);
        Bs[0][br][bc + 0]      = f2tf(pb0.x);
        Bs[0][br][bc + 1]      = f2tf(pb0.y);
        Bs[0][br][bc + 2]      = f2tf(pb0.z);
        Bs[0][br][bc + 3]      = f2tf(pb0.w);
        Bs[0][br][bc + 64]     = f2tf(pb1.x);
        Bs[0][br][bc + 65]     = f2tf(pb1.y);
        Bs[0][br][bc + 66]     = f2tf(pb1.z);
        Bs[0][br][bc + 67]     = f2tf(pb1.w);
    }
    __syncthreads();

    int buf = 0;
    for (int t = 0; t < ntiles; t++) {
        // Prefetch next tile (global -> regs)
        if (t + 1 < ntiles) {
            const int k0 = (t + 1) * 16;
            pa0 = *(const float4*)(Ap + k0);
            pa1 = *(const float4*)(Ap + (size_t)64 * K + k0);
            pb0 = *(const float4*)(Bp + (size_t)k0 * N);
            pb1 = *(const float4*)(Bp + (size_t)k0 * N + 64);
        }

        // Compute on current buffer: 2 k-steps of 8
#pragma unroll
        for (int kk = 0; kk < 16; kk += 8) {
            uint32_t af[2][4], bf[8][2];
#pragma unroll
            for (int mt = 0; mt < 2; mt++) {
                const int r = wm + mt * 16 + gid;
                af[mt][0] = As[buf][kk + tig][r];
                af[mt][1] = As[buf][kk + tig][r + 8];
                af[mt][2] = As[buf][kk + tig + 4][r];
                af[mt][3] = As[buf][kk + tig + 4][r + 8];
            }
#pragma unroll
            for (int nt = 0; nt < 8; nt++) {
                const int c = wn + nt * 8 + gid;
                bf[nt][0] = Bs[buf][kk + tig][c];
                bf[nt][1] = Bs[buf][kk + tig + 4][c];
            }
#pragma unroll
            for (int mt = 0; mt < 2; mt++)
#pragma unroll
                for (int nt = 0; nt < 8; nt++) {
                    asm volatile(
                        "mma.sync.aligned.m16n8k8.row.col.f32.tf32.tf32.f32 "
                        "{%0,%1,%2,%3}, {%4,%5,%6,%7}, {%8,%9}, {%0,%1,%2,%3};"
                        : "+f"(acc[mt][nt][0]), "+f"(acc[mt][nt][1]),
                          "+f"(acc[mt][nt][2]), "+f"(acc[mt][nt][3])
                        : "r"(af[mt][0]), "r"(af[mt][1]), "r"(af[mt][2]), "r"(af[mt][3]),
                          "r"(bf[nt][0]), "r"(bf[nt][1]));
                }
        }

        // Store prefetched tile to other buffer
        if (t + 1 < ntiles) {
            const int nb = buf ^ 1;
            As[nb][ac + 0][ar]      = f2tf(pa0.x);
            As[nb][ac + 1][ar]      = f2tf(pa0.y);
            As[nb][ac + 2][ar]      = f2tf(pa0.z);
            As[nb][ac + 3][ar]      = f2tf(pa0.w);
            As[nb][ac + 0][ar + 64] = f2tf(pa1.x);
            As[nb][ac + 1][ar + 64] = f2tf(pa1.y);
            As[nb][ac + 2][ar + 64] = f2tf(pa1.z);
            As[nb][ac + 3][ar + 64] = f2tf(pa1.w);
            Bs[nb][br][bc + 0]      = f2tf(pb0.x);
            Bs[nb][br][bc + 1]      = f2tf(pb0.y);
            Bs[nb][br][bc + 2]      = f2tf(pb0.z);
            Bs[nb][br][bc + 3]      = f2tf(pb0.w);
            Bs[nb][br][bc + 64]     = f2tf(pb1.x);
            Bs[nb][br][bc + 65]     = f2tf(pb1.y);
            Bs[nb][br][bc + 66]     = f2tf(pb1.z);
            Bs[nb][br][bc + 67]     = f2tf(pb1.w);
        }
        __syncthreads();
        buf ^= 1;
    }

    // Epilogue with bias
#pragma unroll
    for (int mt = 0; mt < 2; mt++) {
        const int r0 = bm + wm + mt * 16 + gid;
#pragma unroll
        for (int nt = 0; nt < 8; nt++) {
            const int col = bn + wn + nt * 8 + 2 * tig;
            const float bx = bias[col], by = bias[col + 1];
            float2 v0 = {acc[mt][nt][0] + bx, acc[mt][nt][1] + by};
            float2 v1 = {acc[mt][nt][2] + bx, acc[mt][nt][3] + by};
            *(float2*)(C + (size_t)r0 * N + col)       = v0;
            *(float2*)(C + (size_t)(r0 + 8) * N + col) = v1;
        }
    }
}

// ---------------------------------------------------------------------------
// Flash attention (causal, fp32 online softmax). Unchanged from round 1.
// grid = (T/64, H, B); block = 64 threads; thread t owns query row t of tile.
// ---------------------------------------------------------------------------
__global__ __launch_bounds__(64) void flash_attn_kernel(
    const float* __restrict__ qkv, float* __restrict__ y)
{
    __shared__ float ks[64][64];
    __shared__ float vs[64][64];
    __shared__ float ss[64][64];   // transposed: ss[key][query_row]

    const int row = threadIdx.x;
    const int qt0 = blockIdx.x * 64;
    const int h   = blockIdx.y;
    const int b   = blockIdx.z;
    const int qi  = qt0 + row;
    const float scale = 0.125f;

    float4 q[16];
    {
        const float* qptr = qkv + ((size_t)(b * SEQ + qi) * 3 * DM) + h * HD;
#pragma unroll
        for (int i = 0; i < 16; i++) q[i] = ((const float4*)qptr)[i];
    }

    float o[64];
#pragma unroll
    for (int d = 0; d < 64; d++) o[d] = 0.f;
    float m = -1e30f, l = 0.f;

    const int ntiles = qt0 / 64 + 1;
    for (int kt = 0; kt < ntiles; kt++) {
        const int kt0 = kt * 64;
        {
            const float* kptr = qkv + ((size_t)(b * SEQ + kt0 + row) * 3 * DM) + DM + h * HD;
            const float* vptr = kptr + DM;
#pragma unroll
            for (int i = 0; i < 16; i++) {
                ((float4*)ks[row])[i] = ((const float4*)kptr)[i];
                ((float4*)vs[row])[i] = ((const float4*)vptr)[i];
            }
        }
        __syncthreads();

        float mt = -1e30f;
        for (int j = 0; j < 64; j++) {
            const float4* kk = (const float4*)ks[j];
            float s0 = 0.f, s1 = 0.f, s2 = 0.f, s3 = 0.f;
#pragma unroll
            for (int i = 0; i < 16; i++) {
                float4 k4 = kk[i];
                float4 qv = q[i];
                s0 += qv.x * k4.x;
                s1 += qv.y * k4.y;
                s2 += qv.z * k4.z;
                s3 += qv.w * k4.w;
            }
            float s = ((s0 + s1) + (s2 + s3)) * scale;
            if (kt0 + j > qi) s = -1e30f;
            ss[j][row] = s;
            mt = fmaxf(mt, s);
        }

        const float mnew = fmaxf(m, mt);
        const float corr = __expf(m - mnew);
        l *= corr;
#pragma unroll
        for (int d = 0; d < 64; d++) o[d] *= corr;
        m = mnew;

        for (int j = 0; j < 64; j++) {
            const float p = __expf(ss[j][row] - mnew);
            l += p;
            const float4* vv = (const float4*)vs[j];
#pragma unroll
            for (int i = 0; i < 16; i++) {
                float4 v4 = vv[i];
                o[4 * i + 0] += p * v4.x;
                o[4 * i + 1] += p * v4.y;
                o[4 * i + 2] += p * v4.z;
                o[4 * i + 3] += p * v4.w;
            }
        }
        __syncthreads();
    }

    const float inv = 1.f / l;
    float* yptr = y + (size_t)(b * SEQ + qi) * DM + h * HD;
#pragma unroll
    for (int d = 0; d < 64; d += 4) {
        float4 t;
        t.x = o[d + 0] * inv;
        t.y = o[d + 1] * inv;
        t.z = o[d + 2] * inv;
        t.w = o[d + 3] * inv;
        *(float4*)(yptr + d) = t;
    }
}

// ---------------------------------------------------------------------------
// Launch
// ---------------------------------------------------------------------------
extern "C" void kernel_launch(void* const* d_in, const int* in_sizes, int n_in,
                              void* d_out, int out_size)
{
    (void)in_sizes; (void)n_in; (void)out_size;
    const float* x      = (const float*)d_in[0];
    const float* w_qkv  = (const float*)d_in[1];
    const float* b_qkv  = (const float*)d_in[2];
    const float* w_proj = (const float*)d_in[3];
    const float* b_proj = (const float*)d_in[4];
    float* out = (float*)d_out;

    float* qkv = nullptr;
    float* y   = nullptr;
    cudaGetSymbolAddress((void**)&qkv, g_qkv);
    cudaGetSymbolAddress((void**)&y,   g_y);

    // 1) QKV projection: [8192,1024] @ [1024,3072] + b
    tf32_gemm_bias<<<dim3(3 * DM / 128, M_ROWS / 128), 256>>>(
        x, w_qkv, b_qkv, qkv, M_ROWS, 3 * DM, DM);

    // 2) Causal flash attention
    flash_attn_kernel<<<dim3(SEQ / 64, NH, BATCH), 64>>>(qkv, y);

    // 3) Output projection: [8192,1024] @ [1024,1024] + b
    tf32_gemm_bias<<<dim3(DM / 128, M_ROWS / 128), 256>>>(
        y, w_proj, b_proj, out, M_ROWS, DM, DM);
}

// round 5
// speedup vs baseline: 3.0782x; 2.2170x over previous
#include <cuda_runtime.h>
#include <cuda_bf16.h>
#include <cstdint>

// Problem constants
#define BATCH 4
#define SEQ   2048
#define DM    1024
#define NH    16
#define HD    64
#define M_ROWS (BATCH*SEQ)   // 8192

// Scratch (device globals; no allocation allowed)
__device__ float g_qkv[(size_t)M_ROWS * 3 * DM];   // [B*T, 3*C] (sel, head, hd)
__device__ float g_y[(size_t)M_ROWS * DM];         // [B*T, C]

__device__ __forceinline__ uint32_t f2tf(float f) {
    uint32_t u;
    asm("cvt.rna.tf32.f32 %0, %1;" : "=r"(u) : "f"(f));
    return u;
}

#define MMA_TF32(acc, a, b0v, b1v)                                              \
    asm volatile(                                                               \
        "mma.sync.aligned.m16n8k8.row.col.f32.tf32.tf32.f32 "                   \
        "{%0,%1,%2,%3}, {%4,%5,%6,%7}, {%8,%9}, {%0,%1,%2,%3};"                 \
        : "+f"(acc[0]), "+f"(acc[1]), "+f"(acc[2]), "+f"(acc[3])                \
        : "r"(a[0]), "r"(a[1]), "r"(a[2]), "r"(a[3]), "r"(b0v), "r"(b1v))

// ---------------------------------------------------------------------------
// TF32 tensor-core GEMM with bias (unchanged from round 2).
// ---------------------------------------------------------------------------
#define TFS 136

__global__ __launch_bounds__(256) void tf32_gemm_bias(
    const float* __restrict__ A, const float* __restrict__ B,
    const float* __restrict__ bias, float* __restrict__ C,
    int M, int N, int K)
{
    __shared__ uint32_t As[2][16][TFS];
    __shared__ uint32_t Bs[2][16][TFS];

    const int tid  = threadIdx.x;
    const int lane = tid & 31;
    const int wid  = tid >> 5;
    const int gid  = lane >> 2;
    const int tig  = lane & 3;
    const int wm   = (wid & 3) * 32;
    const int wn   = (wid >> 2) * 64;
    const int bm   = blockIdx.y * 128;
    const int bn   = blockIdx.x * 128;

    const int ar = tid >> 2;
    const int ac = (tid & 3) * 4;
    const int br = tid >> 4;
    const int bc = (tid & 15) * 4;

    const float* Ap = A + (size_t)(bm + ar) * K + ac;
    const float* Bp = B + (size_t)br * N + bn + bc;

    float acc[2][8][4];
#pragma unroll
    for (int mt = 0; mt < 2; mt++)
#pragma unroll
        for (int nt = 0; nt < 8; nt++)
#pragma unroll
            for (int i = 0; i < 4; i++) acc[mt][nt][i] = 0.f;

    const int ntiles = K / 16;
    float4 pa0, pa1, pb0, pb1;

    {
        pa0 = *(const float4*)(Ap);
        pa1 = *(const float4*)(Ap + (size_t)64 * K);
        pb0 = *(const float4*)(Bp);
        pb1 = *(const float4*)(Bp + 64);
        As[0][ac + 0][ar]      = f2tf(pa0.x);
        As[0][ac + 1][ar]      = f2tf(pa0.y);
        As[0][ac + 2][ar]      = f2tf(pa0.z);
        As[0][ac + 3][ar]      = f2tf(pa0.w);
        As[0][ac + 0][ar + 64] = f2tf(pa1.x);
        As[0][ac + 1][ar + 64] = f2tf(pa1.y);
        As[0][ac + 2][ar + 64] = f2tf(pa1.z);
        As[0][ac + 3][ar + 64] = f2tf(pa1.w);
        Bs[0][br][bc + 0]      = f2tf(pb0.x);
        Bs[0][br][bc + 1]      = f2tf(pb0.y);
        Bs[0][br][bc + 2]      = f2tf(pb0.z);
        Bs[0][br][bc + 3]      = f2tf(pb0.w);
        Bs[0][br][bc + 64]     = f2tf(pb1.x);
        Bs[0][br][bc + 65]     = f2tf(pb1.y);
        Bs[0][br][bc + 66]     = f2tf(pb1.z);
        Bs[0][br][bc + 67]     = f2tf(pb1.w);
    }
    __syncthreads();

    int buf = 0;
    for (int t = 0; t < ntiles; t++) {
        if (t + 1 < ntiles) {
            const int k0 = (t + 1) * 16;
            pa0 = *(const float4*)(Ap + k0);
            pa1 = *(const float4*)(Ap + (size_t)64 * K + k0);
            pb0 = *(const float4*)(Bp + (size_t)k0 * N);
            pb1 = *(const float4*)(Bp + (size_t)k0 * N + 64);
        }

#pragma unroll
        for (int kk = 0; kk < 16; kk += 8) {
            uint32_t af[2][4], bf[8][2];
#pragma unroll
            for (int mt = 0; mt < 2; mt++) {
                const int r = wm + mt * 16 + gid;
                af[mt][0] = As[buf][kk + tig][r];
                af[mt][1] = As[buf][kk + tig][r + 8];
                af[mt][2] = As[buf][kk + tig + 4][r];
                af[mt][3] = As[buf][kk + tig + 4][r + 8];
            }
#pragma unroll
            for (int nt = 0; nt < 8; nt++) {
                const int c = wn + nt * 8 + gid;
                bf[nt][0] = Bs[buf][kk + tig][c];
                bf[nt][1] = Bs[buf][kk + tig + 4][c];
            }
#pragma unroll
            for (int mt = 0; mt < 2; mt++)
#pragma unroll
                for (int nt = 0; nt < 8; nt++)
                    MMA_TF32(acc[mt][nt], af[mt], bf[nt][0], bf[nt][1]);
        }

        if (t + 1 < ntiles) {
            const int nb = buf ^ 1;
            As[nb][ac + 0][ar]      = f2tf(pa0.x);
            As[nb][ac + 1][ar]      = f2tf(pa0.y);
            As[nb][ac + 2][ar]      = f2tf(pa0.z);
            As[nb][ac + 3][ar]      = f2tf(pa0.w);
            As[nb][ac + 0][ar + 64] = f2tf(pa1.x);
            As[nb][ac + 1][ar + 64] = f2tf(pa1.y);
            As[nb][ac + 2][ar + 64] = f2tf(pa1.z);
            As[nb][ac + 3][ar + 64] = f2tf(pa1.w);
            Bs[nb][br][bc + 0]      = f2tf(pb0.x);
            Bs[nb][br][bc + 1]      = f2tf(pb0.y);
            Bs[nb][br][bc + 2]      = f2tf(pb0.z);
            Bs[nb][br][bc + 3]      = f2tf(pb0.w);
            Bs[nb][br][bc + 64]     = f2tf(pb1.x);
            Bs[nb][br][bc + 65]     = f2tf(pb1.y);
            Bs[nb][br][bc + 66]     = f2tf(pb1.z);
            Bs[nb][br][bc + 67]     = f2tf(pb1.w);
        }
        __syncthreads();
        buf ^= 1;
    }

#pragma unroll
    for (int mt = 0; mt < 2; mt++) {
        const int r0 = bm + wm + mt * 16 + gid;
#pragma unroll
        for (int nt = 0; nt < 8; nt++) {
            const int col = bn + wn + nt * 8 + 2 * tig;
            const float bx = bias[col], by = bias[col + 1];
            float2 v0 = {acc[mt][nt][0] + bx, acc[mt][nt][1] + by};
            float2 v1 = {acc[mt][nt][2] + bx, acc[mt][nt][3] + by};
            *(float2*)(C + (size_t)r0 * N + col)       = v0;
            *(float2*)(C + (size_t)(r0 + 8) * N + col) = v1;
        }
    }
}

// ---------------------------------------------------------------------------
// Tensor-core flash attention (causal, tf32 mma, fp32 online softmax).
// grid = (T/64, H, B); block = 128 (4 warps x 16 query rows).
// ks: K tile [key][d] (stride 68 -> conflict-free B-frag loads); reused as
//     P tile [qrow][key] after QK^T (gated by syncthreads).
// vst: V tile TRANSPOSED [d][key] (stride 68 -> conflict-free B-frag loads).
// ---------------------------------------------------------------------------
__global__ __launch_bounds__(128) void flash_attn_tc(
    const float* __restrict__ qkv, float* __restrict__ y)
{
    __shared__ uint32_t ks[64][68];
    __shared__ uint32_t vst[64][68];

    const int tid  = threadIdx.x;
    const int lane = tid & 31;
    const int wid  = tid >> 5;
    const int gid  = lane >> 2;
    const int tig  = lane & 3;
    const int wq   = wid * 16;
    const int qt0  = blockIdx.x * 64;
    const int h    = blockIdx.y;
    const int b    = blockIdx.z;

    // Q fragments (scale 1/sqrt(64) folded in)
    uint32_t qf[8][4];
    {
        const float* q0 = qkv + ((size_t)(b * SEQ + qt0 + wq + gid) * (3 * DM)) + h * HD;
        const float* q1 = q0 + (size_t)8 * 3 * DM;
#pragma unroll
        for (int kk = 0; kk < 8; kk++) {
            qf[kk][0] = f2tf(q0[kk * 8 + tig]     * 0.125f);
            qf[kk][1] = f2tf(q1[kk * 8 + tig]     * 0.125f);
            qf[kk][2] = f2tf(q0[kk * 8 + tig + 4] * 0.125f);
            qf[kk][3] = f2tf(q1[kk * 8 + tig + 4] * 0.125f);
        }
    }

    float o[8][4];
#pragma unroll
    for (int nt = 0; nt < 8; nt++) {
        o[nt][0] = 0.f; o[nt][1] = 0.f; o[nt][2] = 0.f; o[nt][3] = 0.f;
    }
    float m0 = -1e30f, m1 = -1e30f, l0 = 0.f, l1 = 0.f;

    const int ntiles = qt0 / 64 + 1;
    const int krow = tid >> 1;
    const int kcb  = (tid & 1) * 32;

    for (int kt = 0; kt < ntiles; kt++) {
        const int kt0 = kt * 64;

        // Load K/V tile (coalesced float4 gmem; V stored transposed)
        {
            const float* kp = qkv + ((size_t)(b * SEQ + kt0 + krow) * (3 * DM)) + DM + h * HD + kcb;
            const float* vp = kp + DM;
#pragma unroll
            for (int j = 0; j < 32; j += 4) {
                float4 k4 = *(const float4*)(kp + j);
                float4 v4 = *(const float4*)(vp + j);
                ks[krow][kcb + j + 0] = f2tf(k4.x);
                ks[krow][kcb + j + 1] = f2tf(k4.y);
                ks[krow][kcb + j + 2] = f2tf(k4.z);
                ks[krow][kcb + j + 3] = f2tf(k4.w);
                vst[kcb + j + 0][krow] = f2tf(v4.x);
                vst[kcb + j + 1][krow] = f2tf(v4.y);
                vst[kcb + j + 2][krow] = f2tf(v4.z);
                vst[kcb + j + 3][krow] = f2tf(v4.w);
            }
        }
        __syncthreads();

        // S = Q K^T  (warp: 16 rows x 64 keys)
        float acc[8][4];
#pragma unroll
        for (int nt = 0; nt < 8; nt++) {
            acc[nt][0] = 0.f; acc[nt][1] = 0.f; acc[nt][2] = 0.f; acc[nt][3] = 0.f;
        }
#pragma unroll
        for (int kk = 0; kk < 8; kk++) {
            uint32_t bf0[8], bf1[8];
#pragma unroll
            for (int nt = 0; nt < 8; nt++) {
                bf0[nt] = ks[nt * 8 + gid][kk * 8 + tig];
                bf1[nt] = ks[nt * 8 + gid][kk * 8 + tig + 4];
            }
#pragma unroll
            for (int nt = 0; nt < 8; nt++)
                MMA_TF32(acc[nt], qf[kk], bf0[nt], bf1[nt]);
        }
        __syncthreads();   // all warps done reading K -> ks reusable as P

        // Causal mask (diagonal tile only; kt0 == qt0 there)
        if (kt == ntiles - 1) {
            const int r0 = wq + gid, r1 = r0 + 8;
#pragma unroll
            for (int nt = 0; nt < 8; nt++) {
                const int c = nt * 8 + 2 * tig;
                if (c     > r0) acc[nt][0] = -1e30f;
                if (c + 1 > r0) acc[nt][1] = -1e30f;
                if (c     > r1) acc[nt][2] = -1e30f;
                if (c + 1 > r1) acc[nt][3] = -1e30f;
            }
        }

        // Online softmax (rows gid / gid+8; quad reduce over tig)
        float mt0 = -1e30f, mt1 = -1e30f;
#pragma unroll
        for (int nt = 0; nt < 8; nt++) {
            mt0 = fmaxf(mt0, fmaxf(acc[nt][0], acc[nt][1]));
            mt1 = fmaxf(mt1, fmaxf(acc[nt][2], acc[nt][3]));
        }
        mt0 = fmaxf(mt0, __shfl_xor_sync(0xffffffffu, mt0, 1));
        mt0 = fmaxf(mt0, __shfl_xor_sync(0xffffffffu, mt0, 2));
        mt1 = fmaxf(mt1, __shfl_xor_sync(0xffffffffu, mt1, 1));
        mt1 = fmaxf(mt1, __shfl_xor_sync(0xffffffffu, mt1, 2));

        const float mn0 = fmaxf(m0, mt0), mn1 = fmaxf(m1, mt1);
        const float cr0 = __expf(m0 - mn0), cr1 = __expf(m1 - mn1);
        m0 = mn0; m1 = mn1;
        l0 *= cr0; l1 *= cr1;

        float s0 = 0.f, s1 = 0.f;
#pragma unroll
        for (int nt = 0; nt < 8; nt++) {
            const float p0 = __expf(acc[nt][0] - m0);
            const float p1 = __expf(acc[nt][1] - m0);
            const float p2 = __expf(acc[nt][2] - m1);
            const float p3 = __expf(acc[nt][3] - m1);
            s0 += p0 + p1;
            s1 += p2 + p3;
            o[nt][0] *= cr0; o[nt][1] *= cr0; o[nt][2] *= cr1; o[nt][3] *= cr1;
            uint2 w;
            w.x = f2tf(p0); w.y = f2tf(p1);
            *(uint2*)&ks[wq + gid][nt * 8 + 2 * tig] = w;
            w.x = f2tf(p2); w.y = f2tf(p3);
            *(uint2*)&ks[wq + 8 + gid][nt * 8 + 2 * tig] = w;
        }
        s0 += __shfl_xor_sync(0xffffffffu, s0, 1);
        s0 += __shfl_xor_sync(0xffffffffu, s0, 2);
        s1 += __shfl_xor_sync(0xffffffffu, s1, 1);
        s1 += __shfl_xor_sync(0xffffffffu, s1, 2);
        l0 += s0; l1 += s1;
        __syncwarp();   // P visible within warp

        // O += P V  (P rows are warp-private in ks; V from vst)
#pragma unroll
        for (int kk = 0; kk < 8; kk++) {
            uint32_t pa[4];
            pa[0] = ks[wq + gid][kk * 8 + tig];
            pa[1] = ks[wq + 8 + gid][kk * 8 + tig];
            pa[2] = ks[wq + gid][kk * 8 + tig + 4];
            pa[3] = ks[wq + 8 + gid][kk * 8 + tig + 4];
#pragma unroll
            for (int nt = 0; nt < 8; nt++) {
                const uint32_t b0 = vst[nt * 8 + gid][kk * 8 + tig];
                const uint32_t b1 = vst[nt * 8 + gid][kk * 8 + tig + 4];
                MMA_TF32(o[nt], pa, b0, b1);
            }
        }
        __syncthreads();   // before next tile overwrites ks/vst
    }

    // Epilogue: normalize and write y [B*T, DM]
    const float i0 = 1.f / l0, i1 = 1.f / l1;
    float* y0 = y + (size_t)(b * SEQ + qt0 + wq + gid) * DM + h * HD;
    float* y1 = y0 + (size_t)8 * DM;
#pragma unroll
    for (int nt = 0; nt < 8; nt++) {
        const int c = nt * 8 + 2 * tig;
        float2 w0 = {o[nt][0] * i0, o[nt][1] * i0};
        float2 w1 = {o[nt][2] * i1, o[nt][3] * i1};
        *(float2*)(y0 + c) = w0;
        *(float2*)(y1 + c) = w1;
    }
}

// ---------------------------------------------------------------------------
// Launch
// ---------------------------------------------------------------------------
extern "C" void kernel_launch(void* const* d_in, const int* in_sizes, int n_in,
                              void* d_out, int out_size)
{
    (void)in_sizes; (void)n_in; (void)out_size;
    const float* x      = (const float*)d_in[0];
    const float* w_qkv  = (const float*)d_in[1];
    const float* b_qkv  = (const float*)d_in[2];
    const float* w_proj = (const float*)d_in[3];
    const float* b_proj = (const float*)d_in[4];
    float* out = (float*)d_out;

    float* qkv = nullptr;
    float* y   = nullptr;
    cudaGetSymbolAddress((void**)&qkv, g_qkv);
    cudaGetSymbolAddress((void**)&y,   g_y);

    tf32_gemm_bias<<<dim3(3 * DM / 128, M_ROWS / 128), 256>>>(
        x, w_qkv, b_qkv, qkv, M_ROWS, 3 * DM, DM);

    flash_attn_tc<<<dim3(SEQ / 64, NH, BATCH), 128>>>(qkv, y);

    tf32_gemm_bias<<<dim3(DM / 128, M_ROWS / 128), 256>>>(
        y, w_proj, b_proj, out, M_ROWS, DM, DM);
}

// round 7
// speedup vs baseline: 3.5209x; 1.1438x over previous
#include <cuda_runtime.h>
#include <cuda_bf16.h>
#include <cstdint>

// Problem constants
#define BATCH 4
#define SEQ   2048
#define DM    1024
#define NH    16
#define HD    64
#define M_ROWS (BATCH*SEQ)   // 8192

// Scratch (device globals; no allocation allowed)
__device__ float g_qkv[(size_t)M_ROWS * 3 * DM];   // [B*T, 3*C] (sel, head, hd)
__device__ float g_y[(size_t)M_ROWS * DM];         // [B*T, C]

__device__ __forceinline__ uint32_t f2tf(float f) {
    uint32_t u;
    asm("cvt.rna.tf32.f32 %0, %1;" : "=r"(u) : "f"(f));
    return u;
}

#define MMA_TF32(acc, a, b0v, b1v)                                              \
    asm volatile(                                                               \
        "mma.sync.aligned.m16n8k8.row.col.f32.tf32.tf32.f32 "                   \
        "{%0,%1,%2,%3}, {%4,%5,%6,%7}, {%8,%9}, {%0,%1,%2,%3};"                 \
        : "+f"(acc[0]), "+f"(acc[1]), "+f"(acc[2]), "+f"(acc[3])                \
        : "r"(a[0]), "r"(a[1]), "r"(a[2]), "r"(a[3]), "r"(b0v), "r"(b1v))

// ---------------------------------------------------------------------------
// TF32 tensor-core GEMM with bias: C[M,N] = A[M,K] @ B[K,N] + bias[N]
// 128x128 block tile, BK=16 double-buffered, 256 thr (8 warps 4x2),
// warp tile 32x64. __launch_bounds__(256,2): force 2 CTAs/SM (latency hiding).
// ---------------------------------------------------------------------------
#define TFS 136

__global__ __launch_bounds__(256, 2) void tf32_gemm_bias(
    const float* __restrict__ A, const float* __restrict__ B,
    const float* __restrict__ bias, float* __restrict__ C,
    int M, int N, int K)
{
    __shared__ uint32_t As[2][16][TFS];
    __shared__ uint32_t Bs[2][16][TFS];

    const int tid  = threadIdx.x;
    const int lane = tid & 31;
    const int wid  = tid >> 5;
    const int gid  = lane >> 2;
    const int tig  = lane & 3;
    const int wm   = (wid & 3) * 32;
    const int wn   = (wid >> 2) * 64;
    const int bm   = blockIdx.y * 128;
    const int bn   = blockIdx.x * 128;

    const int ar = tid >> 2;
    const int ac = (tid & 3) * 4;
    const int br = tid >> 4;
    const int bc = (tid & 15) * 4;

    const float* Ap = A + (size_t)(bm + ar) * K + ac;
    const float* Bp = B + (size_t)br * N + bn + bc;

    float acc[2][8][4];
#pragma unroll
    for (int mt = 0; mt < 2; mt++)
#pragma unroll
        for (int nt = 0; nt < 8; nt++)
#pragma unroll
            for (int i = 0; i < 4; i++) acc[mt][nt][i] = 0.f;

    const int ntiles = K / 16;
    float4 pa0, pa1, pb0, pb1;

    {
        pa0 = *(const float4*)(Ap);
        pa1 = *(const float4*)(Ap + (size_t)64 * K);
        pb0 = *(const float4*)(Bp);
        pb1 = *(const float4*)(Bp + 64);
        As[0][ac + 0][ar]      = f2tf(pa0.x);
        As[0][ac + 1][ar]      = f2tf(pa0.y);
        As[0][ac + 2][ar]      = f2tf(pa0.z);
        As[0][ac + 3][ar]      = f2tf(pa0.w);
        As[0][ac + 0][ar + 64] = f2tf(pa1.x);
        As[0][ac + 1][ar + 64] = f2tf(pa1.y);
        As[0][ac + 2][ar + 64] = f2tf(pa1.z);
        As[0][ac + 3][ar + 64] = f2tf(pa1.w);
        Bs[0][br][bc + 0]      = f2tf(pb0.x);
        Bs[0][br][bc + 1]      = f2tf(pb0.y);
        Bs[0][br][bc + 2]      = f2tf(pb0.z);
        Bs[0][br][bc + 3]      = f2tf(pb0.w);
        Bs[0][br][bc + 64]     = f2tf(pb1.x);
        Bs[0][br][bc + 65]     = f2tf(pb1.y);
        Bs[0][br][bc + 66]     = f2tf(pb1.z);
        Bs[0][br][bc + 67]     = f2tf(pb1.w);
    }
    __syncthreads();

    int buf = 0;
    for (int t = 0; t < ntiles; t++) {
        if (t + 1 < ntiles) {
            const int k0 = (t + 1) * 16;
            pa0 = *(const float4*)(Ap + k0);
            pa1 = *(const float4*)(Ap + (size_t)64 * K + k0);
            pb0 = *(const float4*)(Bp + (size_t)k0 * N);
            pb1 = *(const float4*)(Bp + (size_t)k0 * N + 64);
        }

#pragma unroll
        for (int kk = 0; kk < 16; kk += 8) {
            uint32_t af[2][4], bf[8][2];
#pragma unroll
            for (int mt = 0; mt < 2; mt++) {
                const int r = wm + mt * 16 + gid;
                af[mt][0] = As[buf][kk + tig][r];
                af[mt][1] = As[buf][kk + tig][r + 8];
                af[mt][2] = As[buf][kk + tig + 4][r];
                af[mt][3] = As[buf][kk + tig + 4][r + 8];
            }
#pragma unroll
            for (int nt = 0; nt < 8; nt++) {
                const int c = wn + nt * 8 + gid;
                bf[nt][0] = Bs[buf][kk + tig][c];
                bf[nt][1] = Bs[buf][kk + tig + 4][c];
            }
#pragma unroll
            for (int mt = 0; mt < 2; mt++)
#pragma unroll
                for (int nt = 0; nt < 8; nt++)
                    MMA_TF32(acc[mt][nt], af[mt], bf[nt][0], bf[nt][1]);
        }

        if (t + 1 < ntiles) {
            const int nb = buf ^ 1;
            As[nb][ac + 0][ar]      = f2tf(pa0.x);
            As[nb][ac + 1][ar]      = f2tf(pa0.y);
            As[nb][ac + 2][ar]      = f2tf(pa0.z);
            As[nb][ac + 3][ar]      = f2tf(pa0.w);
            As[nb][ac + 0][ar + 64] = f2tf(pa1.x);
            As[nb][ac + 1][ar + 64] = f2tf(pa1.y);
            As[nb][ac + 2][ar + 64] = f2tf(pa1.z);
            As[nb][ac + 3][ar + 64] = f2tf(pa1.w);
            Bs[nb][br][bc + 0]      = f2tf(pb0.x);
            Bs[nb][br][bc + 1]      = f2tf(pb0.y);
            Bs[nb][br][bc + 2]      = f2tf(pb0.z);
            Bs[nb][br][bc + 3]      = f2tf(pb0.w);
            Bs[nb][br][bc + 64]     = f2tf(pb1.x);
            Bs[nb][br][bc + 65]     = f2tf(pb1.y);
            Bs[nb][br][bc + 66]     = f2tf(pb1.z);
            Bs[nb][br][bc + 67]     = f2tf(pb1.w);
        }
        __syncthreads();
        buf ^= 1;
    }

#pragma unroll
    for (int mt = 0; mt < 2; mt++) {
        const int r0 = bm + wm + mt * 16 + gid;
#pragma unroll
        for (int nt = 0; nt < 8; nt++) {
            const int col = bn + wn + nt * 8 + 2 * tig;
            const float bx = bias[col], by = bias[col + 1];
            float2 v0 = {acc[mt][nt][0] + bx, acc[mt][nt][1] + by};
            float2 v1 = {acc[mt][nt][2] + bx, acc[mt][nt][3] + by};
            *(float2*)(C + (size_t)r0 * N + col)       = v0;
            *(float2*)(C + (size_t)(r0 + 8) * N + col) = v1;
        }
    }
}

// ---------------------------------------------------------------------------
// Tensor-core flash attention, 128 queries/block (8 warps), P in registers.
// grid = (T/128, H, B); block = 256. Warp w owns query rows wq..wq+15.
// ks:  K tile [key][d]   stride 68 (conflict-free B-frag loads)
// vst: V tile [d][key]   stride 68 (conflict-free B-frag loads + stores)
// P never touches smem: C-frag -> A-frag via width-4 shfl inside each quad.
// ---------------------------------------------------------------------------
__global__ __launch_bounds__(256) void flash_attn_tc(
    const float* __restrict__ qkv, float* __restrict__ y)
{
    __shared__ uint32_t ks[64][68];
    __shared__ uint32_t vst[64][68];

    const int tid  = threadIdx.x;
    const int lane = tid & 31;
    const int wid  = tid >> 5;
    const int gid  = lane >> 2;
    const int tig  = lane & 3;
    const int wq   = wid * 16;
    const int qt0  = (int)(gridDim.x - 1 - blockIdx.x) * 128;  // heavy tiles first
    const int h    = blockIdx.y;
    const int b    = blockIdx.z;

    // Q fragments (scale 1/sqrt(64) folded in)
    uint32_t qf[8][4];
    {
        const float* q0 = qkv + ((size_t)(b * SEQ + qt0 + wq + gid) * (3 * DM)) + h * HD;
        const float* q1 = q0 + (size_t)8 * 3 * DM;
#pragma unroll
        for (int kk = 0; kk < 8; kk++) {
            qf[kk][0] = f2tf(q0[kk * 8 + tig]     * 0.125f);
            qf[kk][1] = f2tf(q1[kk * 8 + tig]     * 0.125f);
            qf[kk][2] = f2tf(q0[kk * 8 + tig + 4] * 0.125f);
            qf[kk][3] = f2tf(q1[kk * 8 + tig + 4] * 0.125f);
        }
    }

    float o[8][4];
#pragma unroll
    for (int nt = 0; nt < 8; nt++) {
        o[nt][0] = 0.f; o[nt][1] = 0.f; o[nt][2] = 0.f; o[nt][3] = 0.f;
    }
    float m0 = -1e30f, m1 = -1e30f, l0 = 0.f, l1 = 0.f;

    const int ntiles = qt0 / 64 + 2;
    const int krow = tid & 63;            // warp lanes -> consecutive rows
    const int kcb  = (tid >> 6) * 16;     // 16-col chunk

    const int src0 = tig >> 1;            // quad-local shfl sources
    const int src2 = (tig >> 1) + 2;
    const bool sel = (tig & 1);

    for (int kt = 0; kt < ntiles; kt++) {
        const int kt0 = kt * 64;

        __syncthreads();   // previous tile fully consumed before overwrite
        {
            const float* kp = qkv + ((size_t)(b * SEQ + kt0 + krow) * (3 * DM)) + DM + h * HD + kcb;
            const float* vp = kp + DM;
#pragma unroll
            for (int j = 0; j < 16; j += 4) {
                float4 k4 = *(const float4*)(kp + j);
                float4 v4 = *(const float4*)(vp + j);
                uint4 w;
                w.x = f2tf(k4.x); w.y = f2tf(k4.y); w.z = f2tf(k4.z); w.w = f2tf(k4.w);
                *(uint4*)&ks[krow][kcb + j] = w;             // conflict-free (row=lane)
                vst[kcb + j + 0][krow] = f2tf(v4.x);         // conflict-free (addr=c*68+lane)
                vst[kcb + j + 1][krow] = f2tf(v4.y);
                vst[kcb + j + 2][krow] = f2tf(v4.z);
                vst[kcb + j + 3][krow] = f2tf(v4.w);
            }
        }
        __syncthreads();

        // Fully-masked warps skip compute (diagonal spillover tile)
        if (kt0 > qt0 + wq + 15) continue;

        // S = Q K^T  (warp: 16 rows x 64 keys)
        float acc[8][4];
#pragma unroll
        for (int nt = 0; nt < 8; nt++) {
            acc[nt][0] = 0.f; acc[nt][1] = 0.f; acc[nt][2] = 0.f; acc[nt][3] = 0.f;
        }
#pragma unroll
        for (int kk = 0; kk < 8; kk++) {
            uint32_t bf0[8], bf1[8];
#pragma unroll
            for (int nt = 0; nt < 8; nt++) {
                bf0[nt] = ks[nt * 8 + gid][kk * 8 + tig];
                bf1[nt] = ks[nt * 8 + gid][kk * 8 + tig + 4];
            }
#pragma unroll
            for (int nt = 0; nt < 8; nt++)
                MMA_TF32(acc[nt], qf[kk], bf0[nt], bf1[nt]);
        }

        // Causal mask (only where keys can exceed rows)
        if (kt0 + 63 > qt0 + wq) {
            const int r0 = qt0 + wq + gid, r1 = r0 + 8;
#pragma unroll
            for (int nt = 0; nt < 8; nt++) {
                const int c = kt0 + nt * 8 + 2 * tig;
                if (c     > r0) acc[nt][0] = -1e30f;
                if (c + 1 > r0) acc[nt][1] = -1e30f;
                if (c     > r1) acc[nt][2] = -1e30f;
                if (c + 1 > r1) acc[nt][3] = -1e30f;
            }
        }

        // Online softmax (rows gid / gid+8; quad reduce over tig)
        float mt0 = -1e30f, mt1 = -1e30f;
#pragma unroll
        for (int nt = 0; nt < 8; nt++) {
            mt0 = fmaxf(mt0, fmaxf(acc[nt][0], acc[nt][1]));
            mt1 = fmaxf(mt1, fmaxf(acc[nt][2], acc[nt][3]));
        }
        mt0 = fmaxf(mt0, __shfl_xor_sync(0xffffffffu, mt0, 1));
        mt0 = fmaxf(mt0, __shfl_xor_sync(0xffffffffu, mt0, 2));
        mt1 = fmaxf(mt1, __shfl_xor_sync(0xffffffffu, mt1, 1));
        mt1 = fmaxf(mt1, __shfl_xor_sync(0xffffffffu, mt1, 2));

        const float mn0 = fmaxf(m0, mt0), mn1 = fmaxf(m1, mt1);
        const float cr0 = __expf(m0 - mn0), cr1 = __expf(m1 - mn1);
        m0 = mn0; m1 = mn1;
        l0 *= cr0; l1 *= cr1;

        // exp -> tf32 P fragments (C-layout), accumulate row sums
        uint32_t pe[8][4];
        float s0 = 0.f, s1 = 0.f;
#pragma unroll
        for (int nt = 0; nt < 8; nt++) {
            const float p0 = __expf(acc[nt][0] - m0);
            const float p1 = __expf(acc[nt][1] - m0);
            const float p2 = __expf(acc[nt][2] - m1);
            const float p3 = __expf(acc[nt][3] - m1);
            s0 += p0 + p1;
            s1 += p2 + p3;
            o[nt][0] *= cr0; o[nt][1] *= cr0; o[nt][2] *= cr1; o[nt][3] *= cr1;
            pe[nt][0] = f2tf(p0); pe[nt][1] = f2tf(p1);
            pe[nt][2] = f2tf(p2); pe[nt][3] = f2tf(p3);
        }
        s0 += __shfl_xor_sync(0xffffffffu, s0, 1);
        s0 += __shfl_xor_sync(0xffffffffu, s0, 2);
        s1 += __shfl_xor_sync(0xffffffffu, s1, 1);
        s1 += __shfl_xor_sync(0xffffffffu, s1, 2);
        l0 += s0; l1 += s1;

        // O += P V : A-fragments assembled from pe via width-4 quad shfl
#pragma unroll
        for (int kk = 0; kk < 8; kk++) {
            uint32_t pa[4];
            {
                const uint32_t u0 = __shfl_sync(0xffffffffu, pe[kk][0], src0, 4);
                const uint32_t u1 = __shfl_sync(0xffffffffu, pe[kk][1], src0, 4);
                pa[0] = sel ? u1 : u0;
                const uint32_t v0 = __shfl_sync(0xffffffffu, pe[kk][2], src0, 4);
                const uint32_t v1 = __shfl_sync(0xffffffffu, pe[kk][3], src0, 4);
                pa[1] = sel ? v1 : v0;
                const uint32_t w0 = __shfl_sync(0xffffffffu, pe[kk][0], src2, 4);
                const uint32_t w1 = __shfl_sync(0xffffffffu, pe[kk][1], src2, 4);
                pa[2] = sel ? w1 : w0;
                const uint32_t x0 = __shfl_sync(0xffffffffu, pe[kk][2], src2, 4);
                const uint32_t x1 = __shfl_sync(0xffffffffu, pe[kk][3], src2, 4);
                pa[3] = sel ? x1 : x0;
            }
#pragma unroll
            for (int nt = 0; nt < 8; nt++) {
                const uint32_t b0 = vst[nt * 8 + gid][kk * 8 + tig];
                const uint32_t b1 = vst[nt * 8 + gid][kk * 8 + tig + 4];
                MMA_TF32(o[nt], pa, b0, b1);
            }
        }
    }

    // Epilogue: normalize and write y [B*T, DM]
    const float i0 = 1.f / l0, i1 = 1.f / l1;
    float* y0 = y + (size_t)(b * SEQ + qt0 + wq + gid) * DM + h * HD;
    float* y1 = y0 + (size_t)8 * DM;
#pragma unroll
    for (int nt = 0; nt < 8; nt++) {
        const int c = nt * 8 + 2 * tig;
        float2 w0 = {o[nt][0] * i0, o[nt][1] * i0};
        float2 w1 = {o[nt][2] * i1, o[nt][3] * i1};
        *(float2*)(y0 + c) = w0;
        *(float2*)(y1 + c) = w1;
    }
}

// ---------------------------------------------------------------------------
// Launch
// ---------------------------------------------------------------------------
extern "C" void kernel_launch(void* const* d_in, const int* in_sizes, int n_in,
                              void* d_out, int out_size)
{
    (void)in_sizes; (void)n_in; (void)out_size;
    const float* x      = (const float*)d_in[0];
    const float* w_qkv  = (const float*)d_in[1];
    const float* b_qkv  = (const float*)d_in[2];
    const float* w_proj = (const float*)d_in[3];
    const float* b_proj = (const float*)d_in[4];
    float* out = (float*)d_out;

    float* qkv = nullptr;
    float* y   = nullptr;
    cudaGetSymbolAddress((void**)&qkv, g_qkv);
    cudaGetSymbolAddress((void**)&y,   g_y);

    // 1) QKV projection: [8192,1024] @ [1024,3072] + b
    tf32_gemm_bias<<<dim3(3 * DM / 128, M_ROWS / 128), 256>>>(
        x, w_qkv, b_qkv, qkv, M_ROWS, 3 * DM, DM);

    // 2) Causal flash attention (128 queries per block)
    flash_attn_tc<<<dim3(SEQ / 128, NH, BATCH), 256>>>(qkv, y);

    // 3) Output projection: [8192,1024] @ [1024,1024] + b
    tf32_gemm_bias<<<dim3(DM / 128, M_ROWS / 128), 256>>>(
        y, w_proj, b_proj, out, M_ROWS, DM, DM);
}